// round 12
// baseline (speedup 1.0000x reference)
#include <cuda_runtime.h>
#include <cstdint>

#define BSZ 4096
#define DD  512
#define HH  1024
#define TW  16
#define NEL (BSZ * HH)

#define BM 128
#define BN 128
#define BK 16
#define FULLMASK 0xFFFFFFFFu

// Packed f32x2 helpers (independent fp32 fma per lane -> bitwise == scalar)
#define PACK2(d, lo, hi) \
    asm("mov.b64 %0, {%1, %2};" : "=l"(d) : "f"(lo), "f"(hi))
#define UNPACK2(lo, hi, d) \
    asm("mov.b64 {%0, %1}, %2;" : "=f"(lo), "=f"(hi) : "l"(d))
#define FMA2(d, a, b) \
    asm("fma.rn.f32x2 %0, %1, %2, %0;" : "+l"(d) : "l"(a), "l"(b))

// ---------------------------------------------------------------------------
// Device scratch (no runtime allocation)
// ---------------------------------------------------------------------------
__device__ float g_z0[NEL];           // fc1(x), time-invariant
__device__ float g_c0[NEL];           // z0 @ w1in^T, time-invariant
__device__ float g_v1[NEL], g_i1[NEL];
__device__ float g_v2[NEL], g_i2[NEL];
__device__ float g_G2[NEL];           // per-step LIF2 input current
__device__ float g_T2[NEL];           // G2 @ w2in^T
__device__ float g_z2[NEL];           // dense z2 (floats 0/1), final output
__device__ float g_w1T[HH * HH];      // w1rec^T
__device__ float g_f2T[HH * HH];      // fc2w^T
__device__ float g_w2T[HH * HH];      // w2rec^T
__device__ unsigned short g_list1[NEL];
__device__ unsigned short g_list2[NEL];
__device__ int g_c1[BSZ], g_c2[BSZ];
__device__ unsigned g_cnt[TW];

// ---------------------------------------------------------------------------
__global__ void init_state() {
    size_t i = (size_t)blockIdx.x * blockDim.x + threadIdx.x;
    size_t st = (size_t)gridDim.x * blockDim.x;
    for (size_t k = i; k < (size_t)NEL; k += st) {
        g_v1[k] = 0.f; g_i1[k] = 0.f; g_v2[k] = 0.f; g_i2[k] = 0.f;
    }
    for (size_t k = i; k < (size_t)BSZ; k += st) { g_c1[k] = 0; g_c2[k] = 0; }
    if (i < TW) g_cnt[i] = 0u;
}

// ---------------------------------------------------------------------------
// FFMA2 SGEMM:  C[M,N] = A[M,K] @ W[N,K]^T (+bias)
// 128 threads/CTA, 128x128 tile, 8x16 microtile as 8x8 f32x2 accumulators.
// Per-element fp32 FMA chain over ascending k -> bitwise == scalar version.
// ---------------------------------------------------------------------------
__global__ __launch_bounds__(128, 2)
void sgemm2(const float* __restrict__ A1, const float* __restrict__ W1,
            const float* __restrict__ bias, float* __restrict__ Cout,
            int K1, int N)
{
    __shared__ __align__(16) float As[2][BK][BM + 4];
    __shared__ __align__(16) float Bs[2][BK][BN + 4];

    const int tid = threadIdx.x;
    const int bn = blockIdx.x, bm = blockIdx.y;
    const int tx = tid & 7;     // 0..7  -> col0 = tx*16
    const int ty = tid >> 3;    // 0..15 -> row0 = ty*8

    unsigned long long acc2[8][8];
#pragma unroll
    for (int i = 0; i < 8; ++i)
#pragma unroll
        for (int j = 0; j < 8; ++j) acc2[i][j] = 0ull;

    const int ntot = K1 / BK;
    float4 ra0, ra1, ra2, ra3, rb0, rb1, rb2, rb3;   // staging (one row each)

    #define LDG2(kt) do {                                                      \
        const float* Ap = A1 + (size_t)(bm * BM + tid) * K1 + (kt) * BK;       \
        const float* Wp = W1 + (size_t)(bn * BN + tid) * K1 + (kt) * BK;       \
        ra0 = ((const float4*)Ap)[0]; ra1 = ((const float4*)Ap)[1];            \
        ra2 = ((const float4*)Ap)[2]; ra3 = ((const float4*)Ap)[3];            \
        rb0 = ((const float4*)Wp)[0]; rb1 = ((const float4*)Wp)[1];            \
        rb2 = ((const float4*)Wp)[2]; rb3 = ((const float4*)Wp)[3];            \
    } while (0)
    #define STS2(buf) do {                                                     \
        As[buf][ 0][tid]=ra0.x; As[buf][ 1][tid]=ra0.y;                        \
        As[buf][ 2][tid]=ra0.z; As[buf][ 3][tid]=ra0.w;                        \
        As[buf][ 4][tid]=ra1.x; As[buf][ 5][tid]=ra1.y;                        \
        As[buf][ 6][tid]=ra1.z; As[buf][ 7][tid]=ra1.w;                        \
        As[buf][ 8][tid]=ra2.x; As[buf][ 9][tid]=ra2.y;                        \
        As[buf][10][tid]=ra2.z; As[buf][11][tid]=ra2.w;                        \
        As[buf][12][tid]=ra3.x; As[buf][13][tid]=ra3.y;                        \
        As[buf][14][tid]=ra3.z; As[buf][15][tid]=ra3.w;                        \
        Bs[buf][ 0][tid]=rb0.x; Bs[buf][ 1][tid]=rb0.y;                        \
        Bs[buf][ 2][tid]=rb0.z; Bs[buf][ 3][tid]=rb0.w;                        \
        Bs[buf][ 4][tid]=rb1.x; Bs[buf][ 5][tid]=rb1.y;                        \
        Bs[buf][ 6][tid]=rb1.z; Bs[buf][ 7][tid]=rb1.w;                        \
        Bs[buf][ 8][tid]=rb2.x; Bs[buf][ 9][tid]=rb2.y;                        \
        Bs[buf][10][tid]=rb2.z; Bs[buf][11][tid]=rb2.w;                        \
        Bs[buf][12][tid]=rb3.x; Bs[buf][13][tid]=rb3.y;                        \
        Bs[buf][14][tid]=rb3.z; Bs[buf][15][tid]=rb3.w;                        \
    } while (0)

    LDG2(0); STS2(0); __syncthreads();

    for (int kt = 0; kt < ntot; ++kt) {
        const int cur = kt & 1;
        const bool more = (kt + 1 < ntot);
        if (more) LDG2(kt + 1);

#pragma unroll
        for (int k = 0; k < BK; ++k) {
            const float4 av0 = *(const float4*)&As[cur][k][ty * 8];
            const float4 av1 = *(const float4*)&As[cur][k][ty * 8 + 4];
            const float4 bv0 = *(const float4*)&Bs[cur][k][tx * 16];
            const float4 bv1 = *(const float4*)&Bs[cur][k][tx * 16 + 4];
            const float4 bv2 = *(const float4*)&Bs[cur][k][tx * 16 + 8];
            const float4 bv3 = *(const float4*)&Bs[cur][k][tx * 16 + 12];

            unsigned long long a2[8], b2[8];
            PACK2(a2[0], av0.x, av0.x); PACK2(a2[1], av0.y, av0.y);
            PACK2(a2[2], av0.z, av0.z); PACK2(a2[3], av0.w, av0.w);
            PACK2(a2[4], av1.x, av1.x); PACK2(a2[5], av1.y, av1.y);
            PACK2(a2[6], av1.z, av1.z); PACK2(a2[7], av1.w, av1.w);
            PACK2(b2[0], bv0.x, bv0.y); PACK2(b2[1], bv0.z, bv0.w);
            PACK2(b2[2], bv1.x, bv1.y); PACK2(b2[3], bv1.z, bv1.w);
            PACK2(b2[4], bv2.x, bv2.y); PACK2(b2[5], bv2.z, bv2.w);
            PACK2(b2[6], bv3.x, bv3.y); PACK2(b2[7], bv3.z, bv3.w);

#pragma unroll
            for (int i = 0; i < 8; ++i)
#pragma unroll
                for (int j = 0; j < 8; ++j)
                    FMA2(acc2[i][j], a2[i], b2[j]);
        }
        if (more) { STS2(cur ^ 1); __syncthreads(); }
    }

    const int m0 = bm * BM + ty * 8;
    const int n0 = bn * BN + tx * 16;
#pragma unroll
    for (int i = 0; i < 8; ++i) {
        size_t row = (size_t)(m0 + i) * N + n0;
#pragma unroll
        for (int j = 0; j < 8; ++j) {
            float lo, hi;
            UNPACK2(lo, hi, acc2[i][j]);
            if (bias) { lo += bias[n0 + 2 * j]; hi += bias[n0 + 2 * j + 1]; }
            Cout[row + 2 * j] = lo;
            Cout[row + 2 * j + 1] = hi;
        }
    }
}

__global__ void transpose_hh(const float* __restrict__ in, float* __restrict__ out) {
    __shared__ float t[32][33];
    int x = blockIdx.x * 32 + threadIdx.x, y = blockIdx.y * 32 + threadIdx.y;
    for (int j = 0; j < 32; j += 8)
        t[threadIdx.y + j][threadIdx.x] = in[(size_t)(y + j) * HH + x];
    __syncthreads();
    x = blockIdx.y * 32 + threadIdx.x; y = blockIdx.x * 32 + threadIdx.y;
    for (int j = 0; j < 32; j += 8)
        out[(size_t)(y + j) * HH + x] = t[threadIdx.x][threadIdx.y + j];
}

// ---------------------------------------------------------------------------
// Sparse helpers: acc[j] += WT[k][col+j] over active k ASCENDING.
// Bitwise equal to the dense fp32 FMA chain (z=1 adds w exactly; z=0 no-op).
// ---------------------------------------------------------------------------
__device__ __forceinline__ void sparse_accum(float acc[8], const float* __restrict__ WT,
                                             const unsigned short* __restrict__ sl,
                                             int cnt, int col)
{
    int i = 0;
    for (; i + 4 <= cnt; i += 4) {
        const int k0 = sl[i], k1 = sl[i + 1], k2 = sl[i + 2], k3 = sl[i + 3];
        const float4* p0 = (const float4*)(WT + (size_t)k0 * HH + col);
        const float4* p1 = (const float4*)(WT + (size_t)k1 * HH + col);
        const float4* p2 = (const float4*)(WT + (size_t)k2 * HH + col);
        const float4* p3 = (const float4*)(WT + (size_t)k3 * HH + col);
        float4 a0 = p0[0], a1 = p0[1];
        float4 b0 = p1[0], b1 = p1[1];
        float4 c0 = p2[0], c1 = p2[1];
        float4 d0 = p3[0], d1 = p3[1];
        acc[0] += a0.x; acc[1] += a0.y; acc[2] += a0.z; acc[3] += a0.w;
        acc[4] += a1.x; acc[5] += a1.y; acc[6] += a1.z; acc[7] += a1.w;
        acc[0] += b0.x; acc[1] += b0.y; acc[2] += b0.z; acc[3] += b0.w;
        acc[4] += b1.x; acc[5] += b1.y; acc[6] += b1.z; acc[7] += b1.w;
        acc[0] += c0.x; acc[1] += c0.y; acc[2] += c0.z; acc[3] += c0.w;
        acc[4] += c1.x; acc[5] += c1.y; acc[6] += c1.z; acc[7] += c1.w;
        acc[0] += d0.x; acc[1] += d0.y; acc[2] += d0.z; acc[3] += d0.w;
        acc[4] += d1.x; acc[5] += d1.y; acc[6] += d1.z; acc[7] += d1.w;
    }
    for (; i < cnt; ++i) {
        const int k = sl[i];
        const float4* p = (const float4*)(WT + (size_t)k * HH + col);
        float4 a0 = p[0], a1 = p[1];
        acc[0] += a0.x; acc[1] += a0.y; acc[2] += a0.z; acc[3] += a0.w;
        acc[4] += a1.x; acc[5] += a1.y; acc[6] += a1.z; acc[7] += a1.w;
    }
}

__device__ __forceinline__ int build_list(unsigned mask, unsigned short* sl,
                                          int* s_w, int lane, int wid, int col)
{
    int myc = __popc(mask);
    int pre = myc;
#pragma unroll
    for (int o = 1; o < 32; o <<= 1) {
        int u = __shfl_up_sync(FULLMASK, pre, o);
        if (lane >= o) pre += u;
    }
    if (lane == 31) s_w[wid] = pre;
    __syncthreads();
    int base = 0;
    for (int w = 0; w < wid; ++w) base += s_w[w];
    int off = base + pre - myc;
#pragma unroll
    for (int j = 0; j < 8; ++j)
        if (mask & (1u << j)) sl[off++] = (unsigned short)(col + j);
    int ncnt = s_w[0] + s_w[1] + s_w[2] + s_w[3];
    __syncthreads();
    return ncnt;
}

// ---------------------------------------------------------------------------
__global__ __launch_bounds__(128)
void lif1_step(unsigned short* __restrict__ list, int* __restrict__ lcnt,
               const float* __restrict__ W1T, const float* __restrict__ F2T,
               const float* __restrict__ c0v, const float* __restrict__ bias,
               float* __restrict__ V, float* __restrict__ I,
               float* __restrict__ G2)
{
    __shared__ unsigned short s_list[HH];
    __shared__ int s_w[4];
    const int m = blockIdx.x, t = threadIdx.x;
    const int lane = t & 31, wid = t >> 5;
    const int col = t * 8;
    const size_t ridx = (size_t)m * HH + col;

    int cnt = lcnt[m];
    for (int i = t; i < cnt; i += 128) s_list[i] = list[(size_t)m * HH + i];
    __syncthreads();

    float acc[8];
#pragma unroll
    for (int j = 0; j < 8; ++j) acc[j] = 0.f;
    sparse_accum(acc, W1T, s_list, cnt, col);

    float4 v0 = *(const float4*)(V + ridx),   v1 = *(const float4*)(V + ridx + 4);
    float4 i0 = *(const float4*)(I + ridx),   i1 = *(const float4*)(I + ridx + 4);
    float4 q0 = *(const float4*)(c0v + ridx), q1 = *(const float4*)(c0v + ridx + 4);
    float vold[8] = {v0.x, v0.y, v0.z, v0.w, v1.x, v1.y, v1.z, v1.w};
    float iold[8] = {i0.x, i0.y, i0.z, i0.w, i1.x, i1.y, i1.z, i1.w};
    float cin[8]  = {q0.x, q0.y, q0.z, q0.w, q1.x, q1.y, q1.z, q1.w};
    float vn[8], in_[8];
    unsigned mask = 0;
#pragma unroll
    for (int j = 0; j < 8; ++j) {
        float vdec = vold[j] + 0.1f * (iold[j] - vold[j]);
        float z = (vdec > 1.0f) ? 1.0f : 0.0f;
        vn[j] = (1.0f - z) * vdec;
        float idec = iold[j] * 0.8f;
        in_[j] = (idec + cin[j]) + acc[j];
        if (z != 0.0f) mask |= (1u << j);
    }
    *(float4*)(V + ridx)     = make_float4(vn[0], vn[1], vn[2], vn[3]);
    *(float4*)(V + ridx + 4) = make_float4(vn[4], vn[5], vn[6], vn[7]);
    *(float4*)(I + ridx)     = make_float4(in_[0], in_[1], in_[2], in_[3]);
    *(float4*)(I + ridx + 4) = make_float4(in_[4], in_[5], in_[6], in_[7]);

    __syncthreads();
    int ncnt = build_list(mask, s_list, s_w, lane, wid, col);

    for (int i = t; i < ncnt; i += 128) list[(size_t)m * HH + i] = s_list[i];
    if (t == 0) lcnt[m] = ncnt;

    float acc2[8];
#pragma unroll
    for (int j = 0; j < 8; ++j) acc2[j] = 0.f;
    sparse_accum(acc2, F2T, s_list, ncnt, col);
    float4 bb0 = *(const float4*)(bias + col), bb1 = *(const float4*)(bias + col + 4);
    float bv[8] = {bb0.x, bb0.y, bb0.z, bb0.w, bb1.x, bb1.y, bb1.z, bb1.w};
    float g[8];
#pragma unroll
    for (int j = 0; j < 8; ++j) { float v = acc2[j]; v += bv[j]; g[j] = v; }
    *(float4*)(G2 + ridx)     = make_float4(g[0], g[1], g[2], g[3]);
    *(float4*)(G2 + ridx + 4) = make_float4(g[4], g[5], g[6], g[7]);
}

// ---------------------------------------------------------------------------
__global__ __launch_bounds__(128)
void lif2_step(unsigned short* __restrict__ list, int* __restrict__ lcnt,
               const float* __restrict__ W2T, const float* __restrict__ T2,
               float* __restrict__ V, float* __restrict__ I,
               float* __restrict__ Z2, unsigned* __restrict__ cnt_out)
{
    __shared__ unsigned short s_list[HH];
    __shared__ int s_w[4];
    const int m = blockIdx.x, t = threadIdx.x;
    const int lane = t & 31, wid = t >> 5;
    const int col = t * 8;
    const size_t ridx = (size_t)m * HH + col;

    int cnt = lcnt[m];
    for (int i = t; i < cnt; i += 128) s_list[i] = list[(size_t)m * HH + i];
    __syncthreads();

    float4 t0 = *(const float4*)(T2 + ridx), t1 = *(const float4*)(T2 + ridx + 4);
    float acc[8] = {t0.x, t0.y, t0.z, t0.w, t1.x, t1.y, t1.z, t1.w};
    sparse_accum(acc, W2T, s_list, cnt, col);

    float4 v0 = *(const float4*)(V + ridx), v1 = *(const float4*)(V + ridx + 4);
    float4 i0 = *(const float4*)(I + ridx), i1 = *(const float4*)(I + ridx + 4);
    float vold[8] = {v0.x, v0.y, v0.z, v0.w, v1.x, v1.y, v1.z, v1.w};
    float iold[8] = {i0.x, i0.y, i0.z, i0.w, i1.x, i1.y, i1.z, i1.w};
    float vn[8], in_[8], zn[8];
    unsigned mask = 0;
#pragma unroll
    for (int j = 0; j < 8; ++j) {
        float vdec = vold[j] + 0.1f * (iold[j] - vold[j]);
        float z = (vdec > 1.0f) ? 1.0f : 0.0f;
        vn[j] = (1.0f - z) * vdec;
        float idec = iold[j] * 0.8f;
        in_[j] = idec + acc[j];
        zn[j] = z;
        if (z != 0.0f) mask |= (1u << j);
    }
    *(float4*)(V + ridx)     = make_float4(vn[0], vn[1], vn[2], vn[3]);
    *(float4*)(V + ridx + 4) = make_float4(vn[4], vn[5], vn[6], vn[7]);
    *(float4*)(I + ridx)     = make_float4(in_[0], in_[1], in_[2], in_[3]);
    *(float4*)(I + ridx + 4) = make_float4(in_[4], in_[5], in_[6], in_[7]);
    *(float4*)(Z2 + ridx)     = make_float4(zn[0], zn[1], zn[2], zn[3]);
    *(float4*)(Z2 + ridx + 4) = make_float4(zn[4], zn[5], zn[6], zn[7]);

    __syncthreads();
    int ncnt = build_list(mask, s_list, s_w, lane, wid, col);
    for (int i = t; i < ncnt; i += 128) list[(size_t)m * HH + i] = s_list[i];
    if (t == 0) {
        lcnt[m] = ncnt;
        atomicAdd(cnt_out, (unsigned)ncnt);
    }
}

// ---------------------------------------------------------------------------
__global__ void finalize(const float* __restrict__ zlast,
                         const unsigned* __restrict__ cnt,
                         float* __restrict__ out, int n, int out_size)
{
    size_t i = (size_t)blockIdx.x * blockDim.x + threadIdx.x;
    size_t st = (size_t)gridDim.x * blockDim.x;
    for (size_t k = i; k < (size_t)n; k += st) out[k] = zlast[k];
    if (i == 0 && out_size > n) {
        float rs = 0.f;
        for (int t = 0; t < TW; ++t)
            rs += (float)cnt[t] * (1.0f / 4194304.0f);   // exact: /2^22
        out[n] = rs * (1.0f / 16.0f);                     // inv_T, exact
    }
}

// ---------------------------------------------------------------------------
extern "C" void kernel_launch(void* const* d_in, const int* in_sizes, int n_in,
                              void* d_out, int out_size)
{
    const float* x     = (const float*)d_in[0];
    const float* fc1w  = (const float*)d_in[1];
    const float* fc1b  = (const float*)d_in[2];
    const float* w1in  = (const float*)d_in[3];
    const float* w1rec = (const float*)d_in[4];
    const float* fc2w  = (const float*)d_in[5];
    const float* fc2b  = (const float*)d_in[6];
    const float* w2in  = (const float*)d_in[7];
    const float* w2rec = (const float*)d_in[8];
    (void)in_sizes; (void)n_in;

    float *z0, *c0, *v1, *i1, *v2, *i2, *G2, *T2, *z2, *w1T, *f2T, *w2T;
    unsigned short *l1, *l2;
    int *c1, *c2;
    unsigned* cnt;
    cudaGetSymbolAddress((void**)&z0, g_z0);
    cudaGetSymbolAddress((void**)&c0, g_c0);
    cudaGetSymbolAddress((void**)&v1, g_v1);
    cudaGetSymbolAddress((void**)&i1, g_i1);
    cudaGetSymbolAddress((void**)&v2, g_v2);
    cudaGetSymbolAddress((void**)&i2, g_i2);
    cudaGetSymbolAddress((void**)&G2, g_G2);
    cudaGetSymbolAddress((void**)&T2, g_T2);
    cudaGetSymbolAddress((void**)&z2, g_z2);
    cudaGetSymbolAddress((void**)&w1T, g_w1T);
    cudaGetSymbolAddress((void**)&f2T, g_f2T);
    cudaGetSymbolAddress((void**)&w2T, g_w2T);
    cudaGetSymbolAddress((void**)&l1, g_list1);
    cudaGetSymbolAddress((void**)&l2, g_list2);
    cudaGetSymbolAddress((void**)&c1, g_c1);
    cudaGetSymbolAddress((void**)&c2, g_c2);
    cudaGetSymbolAddress((void**)&cnt, g_cnt);

    dim3 grid(HH / BN, BSZ / BM);   // (8, 32)
    dim3 tgrid(32, 32), tblk(32, 8);

    init_state<<<256, 256>>>();

    // ---- one-time prologue ----
    sgemm2<<<grid, 128>>>(x, fc1w, fc1b, z0, DD, HH);     // z0 = fc1(x)
    sgemm2<<<grid, 128>>>(z0, w1in, nullptr, c0, HH, HH); // c0 = z0@w1in^T
    transpose_hh<<<tgrid, tblk>>>(w1rec, w1T);
    transpose_hh<<<tgrid, tblk>>>(fc2w,  f2T);
    transpose_hh<<<tgrid, tblk>>>(w2rec, w2T);

    // ---- time loop: sparse LIF1+G2, dense T2 (FFMA2), sparse LIF2 ----
    for (int t = 0; t < TW; ++t) {
        lif1_step<<<BSZ, 128>>>(l1, c1, w1T, f2T, c0, fc2b, v1, i1, G2);
        sgemm2<<<grid, 128>>>(G2, w2in, nullptr, T2, HH, HH);
        lif2_step<<<BSZ, 128>>>(l2, c2, w2T, T2, v2, i2, z2, cnt + t);
    }

    finalize<<<512, 256>>>(z2, cnt, (float*)d_out, NEL, out_size);
}

// round 13
// speedup vs baseline: 1.6623x; 1.6623x over previous
#include <cuda_runtime.h>
#include <cstdint>

#define BSZ 4096
#define DD  512
#define HH  1024
#define TW  16
#define NEL (BSZ * HH)

#define BM 128
#define BN 128
#define BK 16
#define TM 8
#define TN 8
#define FULLMASK 0xFFFFFFFFu

#define GEMM_BLKS 256
#define LIF_BLKS  4096

// ---------------------------------------------------------------------------
// Device scratch
// ---------------------------------------------------------------------------
__device__ float g_z0[NEL];
__device__ float g_c0[NEL];
__device__ float g_v1[NEL], g_i1[NEL];
__device__ float g_v2[NEL], g_i2[NEL];
__device__ float g_G2[2][NEL];        // parity-buffered LIF2 input current
__device__ float g_T2[2][NEL];        // parity-buffered G2 @ w2in^T
__device__ float g_z2[NEL];
__device__ float g_w1T[HH * HH];
__device__ float g_f2T[HH * HH];
__device__ float g_w2T[HH * HH];
__device__ unsigned short g_list1[NEL];
__device__ unsigned short g_list2[NEL];
__device__ int g_c1[BSZ], g_c2[BSZ];
__device__ unsigned g_cnt[TW];

struct LifSmem { unsigned short list[HH]; int sw[8]; };

// ---------------------------------------------------------------------------
__global__ void init_state() {
    size_t i = (size_t)blockIdx.x * blockDim.x + threadIdx.x;
    size_t st = (size_t)gridDim.x * blockDim.x;
    for (size_t k = i; k < (size_t)NEL; k += st) {
        g_v1[k] = 0.f; g_i1[k] = 0.f; g_v2[k] = 0.f; g_i2[k] = 0.f;
    }
    for (size_t k = i; k < (size_t)BSZ; k += st) { g_c1[k] = 0; g_c2[k] = 0; }
    if (i < TW) g_cnt[i] = 0u;
}

// ---------------------------------------------------------------------------
// Dense GEMM body (R6/R11-proven, 256 threads): C = A @ W^T (+bias)
// Operates on caller-provided smem (As: 2*16*132 floats, Bs after it).
// ---------------------------------------------------------------------------
__device__ __forceinline__ void gemm_body(
    float* __restrict__ Asf, float* __restrict__ Bsf,
    const float* __restrict__ A1, const float* __restrict__ W1,
    const float* __restrict__ bias, float* __restrict__ Cout,
    int K1, int N, int bn, int bm, int tid)
{
    const int tx = tid & 15, ty = tid >> 4;
    const int lrow = tid >> 2, lcol = (tid & 3) << 2;
    #define AS_(b, k, x) Asf[((b) * BK + (k)) * (BM + 4) + (x)]
    #define BS_(b, k, x) Bsf[((b) * BK + (k)) * (BN + 4) + (x)]

    float acc[TM][TN];
#pragma unroll
    for (int i = 0; i < TM; ++i)
#pragma unroll
        for (int j = 0; j < TN; ++j) acc[i][j] = 0.f;

    const int ntot = K1 / BK;
    float4 ra0, ra1, rb0, rb1;

    #define LDGT(kt) do {                                                      \
        const float* Ap = A1 + (size_t)(bm * BM + lrow) * K1 + (kt) * BK + lcol;\
        const float* Wp = W1 + (size_t)(bn * BN + lrow) * K1 + (kt) * BK + lcol;\
        ra0 = *(const float4*)Ap; ra1 = *(const float4*)(Ap + (size_t)64 * K1); \
        rb0 = *(const float4*)Wp; rb1 = *(const float4*)(Wp + (size_t)64 * K1); \
    } while (0)
    #define STST(buf) do {                                                     \
        AS_(buf, lcol + 0, lrow) = ra0.x; AS_(buf, lcol + 1, lrow) = ra0.y;    \
        AS_(buf, lcol + 2, lrow) = ra0.z; AS_(buf, lcol + 3, lrow) = ra0.w;    \
        AS_(buf, lcol + 0, lrow + 64) = ra1.x; AS_(buf, lcol + 1, lrow + 64) = ra1.y; \
        AS_(buf, lcol + 2, lrow + 64) = ra1.z; AS_(buf, lcol + 3, lrow + 64) = ra1.w; \
        BS_(buf, lcol + 0, lrow) = rb0.x; BS_(buf, lcol + 1, lrow) = rb0.y;    \
        BS_(buf, lcol + 2, lrow) = rb0.z; BS_(buf, lcol + 3, lrow) = rb0.w;    \
        BS_(buf, lcol + 0, lrow + 64) = rb1.x; BS_(buf, lcol + 1, lrow + 64) = rb1.y; \
        BS_(buf, lcol + 2, lrow + 64) = rb1.z; BS_(buf, lcol + 3, lrow + 64) = rb1.w; \
    } while (0)

    LDGT(0); STST(0); __syncthreads();
    for (int kt = 0; kt < ntot; ++kt) {
        const int cur = kt & 1;
        const bool more = (kt + 1 < ntot);
        if (more) LDGT(kt + 1);
#pragma unroll
        for (int k = 0; k < BK; ++k) {
            const float4 av0 = *(const float4*)&AS_(cur, k, ty * TM);
            const float4 av1 = *(const float4*)&AS_(cur, k, ty * TM + 4);
            const float4 bv0 = *(const float4*)&BS_(cur, k, tx * TN);
            const float4 bv1 = *(const float4*)&BS_(cur, k, tx * TN + 4);
            float a[TM] = {av0.x, av0.y, av0.z, av0.w, av1.x, av1.y, av1.z, av1.w};
            float b[TN] = {bv0.x, bv0.y, bv0.z, bv0.w, bv1.x, bv1.y, bv1.z, bv1.w};
#pragma unroll
            for (int i = 0; i < TM; ++i)
#pragma unroll
                for (int j = 0; j < TN; ++j) acc[i][j] += a[i] * b[j];
        }
        if (more) { STST(cur ^ 1); __syncthreads(); }
    }
    const int m0 = bm * BM + ty * TM, n0 = bn * BN + tx * TN;
#pragma unroll
    for (int i = 0; i < TM; ++i) {
        size_t row = (size_t)(m0 + i) * N + n0;
#pragma unroll
        for (int j = 0; j < TN; ++j) {
            float v = acc[i][j];
            if (bias) v += bias[n0 + j];
            Cout[row + j] = v;
        }
    }
}

// Standalone dense GEMM (prologue)
__global__ __launch_bounds__(256, 2)
void sgemm0(const float* __restrict__ A1, const float* __restrict__ W1,
            const float* __restrict__ bias, float* __restrict__ Cout,
            int K1, int N)
{
    __shared__ __align__(16) float As[2 * BK * (BM + 4)];
    __shared__ __align__(16) float Bs[2 * BK * (BN + 4)];
    gemm_body(As, Bs, A1, W1, bias, Cout, K1, N,
              blockIdx.x, blockIdx.y, threadIdx.x);
}

__global__ void transpose_hh(const float* __restrict__ in, float* __restrict__ out) {
    __shared__ float t[32][33];
    int x = blockIdx.x * 32 + threadIdx.x, y = blockIdx.y * 32 + threadIdx.y;
    for (int j = 0; j < 32; j += 8)
        t[threadIdx.y + j][threadIdx.x] = in[(size_t)(y + j) * HH + x];
    __syncthreads();
    x = blockIdx.y * 32 + threadIdx.x; y = blockIdx.x * 32 + threadIdx.y;
    for (int j = 0; j < 32; j += 8)
        out[(size_t)(y + j) * HH + x] = t[threadIdx.x][threadIdx.y + j];
}

// ---------------------------------------------------------------------------
// Sparse helpers, 256-thread layout: thread t owns cols t*4..t*4+3.
// Per-column ascending-k fp32 add chain -> bitwise == dense FMA chain.
// ---------------------------------------------------------------------------
__device__ __forceinline__ void sparse_accum4(float acc[4], const float* __restrict__ WT,
                                              const unsigned short* __restrict__ sl,
                                              int cnt, int col)
{
    int i = 0;
    for (; i + 4 <= cnt; i += 4) {
        const int k0 = sl[i], k1 = sl[i + 1], k2 = sl[i + 2], k3 = sl[i + 3];
        float4 a = *(const float4*)(WT + (size_t)k0 * HH + col);
        float4 b = *(const float4*)(WT + (size_t)k1 * HH + col);
        float4 c = *(const float4*)(WT + (size_t)k2 * HH + col);
        float4 d = *(const float4*)(WT + (size_t)k3 * HH + col);
        acc[0] += a.x; acc[1] += a.y; acc[2] += a.z; acc[3] += a.w;
        acc[0] += b.x; acc[1] += b.y; acc[2] += b.z; acc[3] += b.w;
        acc[0] += c.x; acc[1] += c.y; acc[2] += c.z; acc[3] += c.w;
        acc[0] += d.x; acc[1] += d.y; acc[2] += d.z; acc[3] += d.w;
    }
    for (; i < cnt; ++i) {
        const int k = sl[i];
        float4 a = *(const float4*)(WT + (size_t)k * HH + col);
        acc[0] += a.x; acc[1] += a.y; acc[2] += a.z; acc[3] += a.w;
    }
}

__device__ __forceinline__ int build_list256(unsigned mask, unsigned short* sl,
                                             int* s_w, int lane, int wid, int col)
{
    int myc = __popc(mask);
    int pre = myc;
#pragma unroll
    for (int o = 1; o < 32; o <<= 1) {
        int u = __shfl_up_sync(FULLMASK, pre, o);
        if (lane >= o) pre += u;
    }
    if (lane == 31) s_w[wid] = pre;
    __syncthreads();
    int base = 0;
    for (int w = 0; w < wid; ++w) base += s_w[w];
    int off = base + pre - myc;
#pragma unroll
    for (int j = 0; j < 4; ++j)
        if (mask & (1u << j)) sl[off++] = (unsigned short)(col + j);
    int ncnt = 0;
#pragma unroll
    for (int w = 0; w < 8; ++w) ncnt += s_w[w];
    __syncthreads();
    return ncnt;
}

// ---------------------------------------------------------------------------
__device__ __forceinline__ void lif1_body(LifSmem* ls, int m, int tid,
    unsigned short* __restrict__ list, int* __restrict__ lcnt,
    const float* __restrict__ W1T, const float* __restrict__ F2T,
    const float* __restrict__ c0v, const float* __restrict__ bias,
    float* __restrict__ V, float* __restrict__ I, float* __restrict__ G2w)
{
    const int lane = tid & 31, wid = tid >> 5;
    const int col = tid * 4;
    const size_t ridx = (size_t)m * HH + col;

    int cnt = lcnt[m];
    for (int i = tid; i < cnt; i += 256) ls->list[i] = list[(size_t)m * HH + i];
    __syncthreads();

    float acc[4] = {0.f, 0.f, 0.f, 0.f};
    sparse_accum4(acc, W1T, ls->list, cnt, col);

    float4 v4 = *(const float4*)(V + ridx);
    float4 i4 = *(const float4*)(I + ridx);
    float4 q4 = *(const float4*)(c0v + ridx);
    float vo[4] = {v4.x, v4.y, v4.z, v4.w};
    float io[4] = {i4.x, i4.y, i4.z, i4.w};
    float cq[4] = {q4.x, q4.y, q4.z, q4.w};
    float vn[4], in_[4];
    unsigned mask = 0;
#pragma unroll
    for (int j = 0; j < 4; ++j) {
        float vdec = vo[j] + 0.1f * (io[j] - vo[j]);
        float z = (vdec > 1.0f) ? 1.0f : 0.0f;
        vn[j] = (1.0f - z) * vdec;
        float idec = io[j] * 0.8f;
        in_[j] = (idec + cq[j]) + acc[j];
        if (z != 0.0f) mask |= (1u << j);
    }
    *(float4*)(V + ridx) = make_float4(vn[0], vn[1], vn[2], vn[3]);
    *(float4*)(I + ridx) = make_float4(in_[0], in_[1], in_[2], in_[3]);

    __syncthreads();
    int ncnt = build_list256(mask, ls->list, ls->sw, lane, wid, col);
    for (int i = tid; i < ncnt; i += 256) list[(size_t)m * HH + i] = ls->list[i];
    if (tid == 0) lcnt[m] = ncnt;

    float acc2[4] = {0.f, 0.f, 0.f, 0.f};
    sparse_accum4(acc2, F2T, ls->list, ncnt, col);
    float4 b4 = *(const float4*)(bias + col);
    float bv[4] = {b4.x, b4.y, b4.z, b4.w};
    float g[4];
#pragma unroll
    for (int j = 0; j < 4; ++j) { float v = acc2[j]; v += bv[j]; g[j] = v; }
    *(float4*)(G2w + ridx) = make_float4(g[0], g[1], g[2], g[3]);
}

__device__ __forceinline__ void lif2_body(LifSmem* ls, int m, int tid,
    unsigned short* __restrict__ list, int* __restrict__ lcnt,
    const float* __restrict__ W2T, const float* __restrict__ T2r,
    float* __restrict__ V, float* __restrict__ I,
    float* __restrict__ Z2, unsigned* __restrict__ cnt_out)
{
    const int lane = tid & 31, wid = tid >> 5;
    const int col = tid * 4;
    const size_t ridx = (size_t)m * HH + col;

    int cnt = lcnt[m];
    for (int i = tid; i < cnt; i += 256) ls->list[i] = list[(size_t)m * HH + i];
    __syncthreads();

    float4 t4 = *(const float4*)(T2r + ridx);
    float acc[4] = {t4.x, t4.y, t4.z, t4.w};
    sparse_accum4(acc, W2T, ls->list, cnt, col);

    float4 v4 = *(const float4*)(V + ridx);
    float4 i4 = *(const float4*)(I + ridx);
    float vo[4] = {v4.x, v4.y, v4.z, v4.w};
    float io[4] = {i4.x, i4.y, i4.z, i4.w};
    float vn[4], in_[4], zn[4];
    unsigned mask = 0;
#pragma unroll
    for (int j = 0; j < 4; ++j) {
        float vdec = vo[j] + 0.1f * (io[j] - vo[j]);
        float z = (vdec > 1.0f) ? 1.0f : 0.0f;
        vn[j] = (1.0f - z) * vdec;
        float idec = io[j] * 0.8f;
        in_[j] = idec + acc[j];
        zn[j] = z;
        if (z != 0.0f) mask |= (1u << j);
    }
    *(float4*)(V + ridx)  = make_float4(vn[0], vn[1], vn[2], vn[3]);
    *(float4*)(I + ridx)  = make_float4(in_[0], in_[1], in_[2], in_[3]);
    *(float4*)(Z2 + ridx) = make_float4(zn[0], zn[1], zn[2], zn[3]);

    __syncthreads();
    int ncnt = build_list256(mask, ls->list, ls->sw, lane, wid, col);
    for (int i = tid; i < ncnt; i += 256) list[(size_t)m * HH + i] = ls->list[i];
    if (tid == 0) {
        lcnt[m] = ncnt;
        atomicAdd(cnt_out, (unsigned)ncnt);
    }
}

// ---------------------------------------------------------------------------
// Standalone sparse steps (pipeline head/tail)
// ---------------------------------------------------------------------------
__global__ __launch_bounds__(256)
void lif1_k(unsigned short* list, int* lcnt, const float* W1T, const float* F2T,
            const float* c0v, const float* bias, float* V, float* I, float* G2w)
{
    __shared__ LifSmem ls;
    lif1_body(&ls, blockIdx.x, threadIdx.x, list, lcnt, W1T, F2T, c0v, bias, V, I, G2w);
}

__global__ __launch_bounds__(256)
void lif2_k(unsigned short* list, int* lcnt, const float* W2T, const float* T2r,
            float* V, float* I, float* Z2, unsigned* cnt_out)
{
    __shared__ LifSmem ls;
    lif2_body(&ls, blockIdx.x, threadIdx.x, list, lcnt, W2T, T2r, V, I, Z2, cnt_out);
}

// ---------------------------------------------------------------------------
// Fused step: blocks [0,256) dense GEMM (T2w = G2r @ w2in^T),
//             blocks [256,4352) lif1 of NEXT step (writes G2w),
//             blocks [4352,8448) lif2 of PREVIOUS step (reads T2r).
// All three groups mutually independent; parity buffers remove races.
// ---------------------------------------------------------------------------
__global__ __launch_bounds__(256)
void fused_step(const float* __restrict__ G2r, float* __restrict__ G2w,
                float* __restrict__ T2w, const float* __restrict__ T2r,
                const float* __restrict__ w2in,
                unsigned short* __restrict__ l1, int* __restrict__ c1,
                const float* __restrict__ W1T, const float* __restrict__ F2T,
                const float* __restrict__ c0v, const float* __restrict__ fc2b,
                float* __restrict__ v1, float* __restrict__ i1,
                unsigned short* __restrict__ l2, int* __restrict__ c2,
                const float* __restrict__ W2T,
                float* __restrict__ v2, float* __restrict__ i2,
                float* __restrict__ z2, unsigned* __restrict__ cnt_out,
                int do_lif1, int do_lif2)
{
    __shared__ __align__(16) unsigned char smem_raw[4 * BK * (BM + 4) * 4];
    const int bid = blockIdx.x, tid = threadIdx.x;

    if (bid < GEMM_BLKS) {
        float* Asf = (float*)smem_raw;
        float* Bsf = Asf + 2 * BK * (BM + 4);
        gemm_body(Asf, Bsf, G2r, w2in, nullptr, T2w, HH, HH,
                  bid & 7, bid >> 3, tid);
    } else if (bid < GEMM_BLKS + LIF_BLKS) {
        if (do_lif1)
            lif1_body((LifSmem*)smem_raw, bid - GEMM_BLKS, tid,
                      l1, c1, W1T, F2T, c0v, fc2b, v1, i1, G2w);
    } else {
        if (do_lif2)
            lif2_body((LifSmem*)smem_raw, bid - GEMM_BLKS - LIF_BLKS, tid,
                      l2, c2, W2T, T2r, v2, i2, z2, cnt_out);
    }
}

// ---------------------------------------------------------------------------
__global__ void finalize(const float* __restrict__ zlast,
                         const unsigned* __restrict__ cnt,
                         float* __restrict__ out, int n, int out_size)
{
    size_t i = (size_t)blockIdx.x * blockDim.x + threadIdx.x;
    size_t st = (size_t)gridDim.x * blockDim.x;
    for (size_t k = i; k < (size_t)n; k += st) out[k] = zlast[k];
    if (i == 0 && out_size > n) {
        float rs = 0.f;
        for (int t = 0; t < TW; ++t)
            rs += (float)cnt[t] * (1.0f / 4194304.0f);   // exact: /2^22
        out[n] = rs * (1.0f / 16.0f);                     // inv_T, exact
    }
}

// ---------------------------------------------------------------------------
extern "C" void kernel_launch(void* const* d_in, const int* in_sizes, int n_in,
                              void* d_out, int out_size)
{
    const float* x     = (const float*)d_in[0];
    const float* fc1w  = (const float*)d_in[1];
    const float* fc1b  = (const float*)d_in[2];
    const float* w1in  = (const float*)d_in[3];
    const float* w1rec = (const float*)d_in[4];
    const float* fc2w  = (const float*)d_in[5];
    const float* fc2b  = (const float*)d_in[6];
    const float* w2in  = (const float*)d_in[7];
    const float* w2rec = (const float*)d_in[8];
    (void)in_sizes; (void)n_in;

    float *z0, *c0, *v1, *i1, *v2, *i2, *z2, *w1T, *f2T, *w2T;
    float *G2[2], *T2[2];
    unsigned short *l1, *l2;
    int *c1, *c2;
    unsigned* cnt;
    cudaGetSymbolAddress((void**)&z0, g_z0);
    cudaGetSymbolAddress((void**)&c0, g_c0);
    cudaGetSymbolAddress((void**)&v1, g_v1);
    cudaGetSymbolAddress((void**)&i1, g_i1);
    cudaGetSymbolAddress((void**)&v2, g_v2);
    cudaGetSymbolAddress((void**)&i2, g_i2);
    cudaGetSymbolAddress((void**)&z2, g_z2);
    cudaGetSymbolAddress((void**)&w1T, g_w1T);
    cudaGetSymbolAddress((void**)&f2T, g_f2T);
    cudaGetSymbolAddress((void**)&w2T, g_w2T);
    {
        float* p;
        cudaGetSymbolAddress((void**)&p, g_G2);
        G2[0] = p; G2[1] = p + NEL;
        cudaGetSymbolAddress((void**)&p, g_T2);
        T2[0] = p; T2[1] = p + NEL;
    }
    cudaGetSymbolAddress((void**)&l1, g_list1);
    cudaGetSymbolAddress((void**)&l2, g_list2);
    cudaGetSymbolAddress((void**)&c1, g_c1);
    cudaGetSymbolAddress((void**)&c2, g_c2);
    cudaGetSymbolAddress((void**)&cnt, g_cnt);

    dim3 grid(HH / BN, BSZ / BM);   // (8, 32)
    dim3 tgrid(32, 32), tblk(32, 8);

    init_state<<<256, 256>>>();

    // ---- one-time prologue ----
    sgemm0<<<grid, 256>>>(x, fc1w, fc1b, z0, DD, HH);     // z0 = fc1(x)
    sgemm0<<<grid, 256>>>(z0, w1in, nullptr, c0, HH, HH); // c0 = z0@w1in^T
    transpose_hh<<<tgrid, tblk>>>(w1rec, w1T);
    transpose_hh<<<tgrid, tblk>>>(fc2w,  f2T);
    transpose_hh<<<tgrid, tblk>>>(w2rec, w2T);

    // ---- pipeline head: LIF1 step 0 -> G2[0] ----
    lif1_k<<<LIF_BLKS, 256>>>(l1, c1, w1T, f2T, c0, fc2b, v1, i1, G2[0]);

    // ---- fused loop: sgemm(t) + lif1(t+1) + lif2(t-1) ----
    const int NB = GEMM_BLKS + 2 * LIF_BLKS;
    for (int t = 0; t < TW; ++t) {
        fused_step<<<NB, 256>>>(
            G2[t & 1], G2[(t + 1) & 1],
            T2[t & 1], T2[(t + 1) & 1],
            w2in,
            l1, c1, w1T, f2T, c0, fc2b, v1, i1,
            l2, c2, w2T, v2, i2, z2,
            (t > 0) ? (cnt + t - 1) : cnt,
            (t < TW - 1) ? 1 : 0,     // lif1 of step t+1
            (t > 0) ? 1 : 0);         // lif2 of step t-1
    }

    // ---- pipeline tail: LIF2 step 15 (reads T2[15&1] = T2[1]) ----
    lif2_k<<<LIF_BLKS, 256>>>(l2, c2, w2T, T2[1], v2, i2, z2, cnt + TW - 1);

    finalize<<<512, 256>>>(z2, cnt, (float*)d_out, NEL, out_size);
}

// round 14
// speedup vs baseline: 3.8381x; 2.3089x over previous
#include <cuda_runtime.h>
#include <cstdint>

#define BSZ 4096
#define DD  512
#define HH  1024
#define TW  16
#define NEL (BSZ * HH)

#define BM 128
#define BN 128
#define BK 16
#define TM 8
#define TN 8
#define FULLMASK 0xFFFFFFFFu

#define LIF_BLKS 4096

// ---------------------------------------------------------------------------
// Device scratch
// ---------------------------------------------------------------------------
__device__ float g_z0[NEL];
__device__ float g_c0[NEL];
__device__ float g_v1[NEL], g_i1[NEL];
__device__ float g_v2[NEL], g_i2[NEL];
__device__ float g_z2[NEL];
__device__ float g_w1T[HH * HH];      // w1rec^T
__device__ float g_f2T[HH * HH];      // fc2w^T (for Wc precompute)
__device__ float g_w2T[HH * HH];      // w2rec^T
__device__ float g_Wc[HH * HH];       // w2in @ fc2w
__device__ float g_WcT[HH * HH];      // Wc^T
__device__ float g_bc[HH];            // w2in @ fc2b
__device__ unsigned short g_l1[2][NEL];   // parity-buffered z1 active lists
__device__ unsigned short g_l2[NEL];      // z2 active lists (in-place)
__device__ int g_c1[2][BSZ], g_c2[BSZ];
__device__ unsigned g_cnt[TW];

struct LifSmem { unsigned short la[HH]; unsigned short lb[HH]; int sw[8]; };

// ---------------------------------------------------------------------------
__global__ void init_state() {
    size_t i = (size_t)blockIdx.x * blockDim.x + threadIdx.x;
    size_t st = (size_t)gridDim.x * blockDim.x;
    for (size_t k = i; k < (size_t)NEL; k += st) {
        g_v1[k] = 0.f; g_i1[k] = 0.f; g_v2[k] = 0.f; g_i2[k] = 0.f;
    }
    for (size_t k = i; k < (size_t)BSZ; k += st) {
        g_c1[0][k] = 0; g_c1[1][k] = 0; g_c2[k] = 0;
    }
    if (i < TW) g_cnt[i] = 0u;
}

// ---------------------------------------------------------------------------
// Dense FFMA GEMM (R13-proven): C = A @ W^T (+bias), prologue only
// ---------------------------------------------------------------------------
__global__ __launch_bounds__(256, 2)
void sgemm0(const float* __restrict__ A1, const float* __restrict__ W1,
            const float* __restrict__ bias, float* __restrict__ Cout,
            int K1, int N)
{
    __shared__ __align__(16) float As[2][BK][BM + 4];
    __shared__ __align__(16) float Bs[2][BK][BN + 4];
    const int tid = threadIdx.x, bn = blockIdx.x, bm = blockIdx.y;
    const int tx = tid & 15, ty = tid >> 4;
    const int lrow = tid >> 2, lcol = (tid & 3) << 2;

    float acc[TM][TN];
#pragma unroll
    for (int i = 0; i < TM; ++i)
#pragma unroll
        for (int j = 0; j < TN; ++j) acc[i][j] = 0.f;

    const int ntot = K1 / BK;
    float4 ra0, ra1, rb0, rb1;

    #define LDGT(kt) do {                                                      \
        const float* Ap = A1 + (size_t)(bm * BM + lrow) * K1 + (kt) * BK + lcol;\
        const float* Wp = W1 + (size_t)(bn * BN + lrow) * K1 + (kt) * BK + lcol;\
        ra0 = *(const float4*)Ap; ra1 = *(const float4*)(Ap + (size_t)64 * K1); \
        rb0 = *(const float4*)Wp; rb1 = *(const float4*)(Wp + (size_t)64 * K1); \
    } while (0)
    #define STST(buf) do {                                                     \
        As[buf][lcol+0][lrow]=ra0.x; As[buf][lcol+1][lrow]=ra0.y;              \
        As[buf][lcol+2][lrow]=ra0.z; As[buf][lcol+3][lrow]=ra0.w;              \
        As[buf][lcol+0][lrow+64]=ra1.x; As[buf][lcol+1][lrow+64]=ra1.y;        \
        As[buf][lcol+2][lrow+64]=ra1.z; As[buf][lcol+3][lrow+64]=ra1.w;        \
        Bs[buf][lcol+0][lrow]=rb0.x; Bs[buf][lcol+1][lrow]=rb0.y;              \
        Bs[buf][lcol+2][lrow]=rb0.z; Bs[buf][lcol+3][lrow]=rb0.w;              \
        Bs[buf][lcol+0][lrow+64]=rb1.x; Bs[buf][lcol+1][lrow+64]=rb1.y;        \
        Bs[buf][lcol+2][lrow+64]=rb1.z; Bs[buf][lcol+3][lrow+64]=rb1.w;        \
    } while (0)

    LDGT(0); STST(0); __syncthreads();
    for (int kt = 0; kt < ntot; ++kt) {
        const int cur = kt & 1;
        const bool more = (kt + 1 < ntot);
        if (more) LDGT(kt + 1);
#pragma unroll
        for (int k = 0; k < BK; ++k) {
            const float4 av0 = *(const float4*)&As[cur][k][ty * TM];
            const float4 av1 = *(const float4*)&As[cur][k][ty * TM + 4];
            const float4 bv0 = *(const float4*)&Bs[cur][k][tx * TN];
            const float4 bv1 = *(const float4*)&Bs[cur][k][tx * TN + 4];
            float a[TM] = {av0.x, av0.y, av0.z, av0.w, av1.x, av1.y, av1.z, av1.w};
            float b[TN] = {bv0.x, bv0.y, bv0.z, bv0.w, bv1.x, bv1.y, bv1.z, bv1.w};
#pragma unroll
            for (int i = 0; i < TM; ++i)
#pragma unroll
                for (int j = 0; j < TN; ++j) acc[i][j] += a[i] * b[j];
        }
        if (more) { STST(cur ^ 1); __syncthreads(); }
    }
    const int m0 = bm * BM + ty * TM, n0 = bn * BN + tx * TN;
#pragma unroll
    for (int i = 0; i < TM; ++i) {
        size_t row = (size_t)(m0 + i) * N + n0;
#pragma unroll
        for (int j = 0; j < TN; ++j) {
            float v = acc[i][j];
            if (bias) v += bias[n0 + j];
            Cout[row + j] = v;
        }
    }
}

__global__ void transpose_hh(const float* __restrict__ in, float* __restrict__ out) {
    __shared__ float t[32][33];
    int x = blockIdx.x * 32 + threadIdx.x, y = blockIdx.y * 32 + threadIdx.y;
    for (int j = 0; j < 32; j += 8)
        t[threadIdx.y + j][threadIdx.x] = in[(size_t)(y + j) * HH + x];
    __syncthreads();
    x = blockIdx.y * 32 + threadIdx.x; y = blockIdx.x * 32 + threadIdx.y;
    for (int j = 0; j < 32; j += 8)
        out[(size_t)(y + j) * HH + x] = t[threadIdx.x][threadIdx.y + j];
}

__global__ void bias_prop(const float* __restrict__ w2in, const float* __restrict__ b,
                          float* __restrict__ bc) {
    __shared__ float red[256];
    int n = blockIdx.x; float s = 0.f;
    for (int k = threadIdx.x; k < HH; k += 256) s += w2in[(size_t)n * HH + k] * b[k];
    red[threadIdx.x] = s; __syncthreads();
    for (int o = 128; o; o >>= 1) {
        if (threadIdx.x < o) red[threadIdx.x] += red[threadIdx.x + o];
        __syncthreads();
    }
    if (threadIdx.x == 0) bc[n] = red[0];
}

// ---------------------------------------------------------------------------
// Sparse accumulate: acc[j] += WT[k][col+j] over listed k ASCENDING (float4).
// ---------------------------------------------------------------------------
__device__ __forceinline__ void sparse_accum4(float acc[4], const float* __restrict__ WT,
                                              const unsigned short* __restrict__ sl,
                                              int cnt, int col)
{
    int i = 0;
    for (; i + 4 <= cnt; i += 4) {
        const int k0 = sl[i], k1 = sl[i + 1], k2 = sl[i + 2], k3 = sl[i + 3];
        float4 a = *(const float4*)(WT + (size_t)k0 * HH + col);
        float4 b = *(const float4*)(WT + (size_t)k1 * HH + col);
        float4 c = *(const float4*)(WT + (size_t)k2 * HH + col);
        float4 d = *(const float4*)(WT + (size_t)k3 * HH + col);
        acc[0] += a.x; acc[1] += a.y; acc[2] += a.z; acc[3] += a.w;
        acc[0] += b.x; acc[1] += b.y; acc[2] += b.z; acc[3] += b.w;
        acc[0] += c.x; acc[1] += c.y; acc[2] += c.z; acc[3] += c.w;
        acc[0] += d.x; acc[1] += d.y; acc[2] += d.z; acc[3] += d.w;
    }
    for (; i < cnt; ++i) {
        const int k = sl[i];
        float4 a = *(const float4*)(WT + (size_t)k * HH + col);
        acc[0] += a.x; acc[1] += a.y; acc[2] += a.z; acc[3] += a.w;
    }
}

__device__ __forceinline__ int build_list256(unsigned mask, unsigned short* sl,
                                             int* s_w, int lane, int wid, int col)
{
    int myc = __popc(mask);
    int pre = myc;
#pragma unroll
    for (int o = 1; o < 32; o <<= 1) {
        int u = __shfl_up_sync(FULLMASK, pre, o);
        if (lane >= o) pre += u;
    }
    if (lane == 31) s_w[wid] = pre;
    __syncthreads();
    int base = 0;
    for (int w = 0; w < wid; ++w) base += s_w[w];
    int off = base + pre - myc;
#pragma unroll
    for (int j = 0; j < 4; ++j)
        if (mask & (1u << j)) sl[off++] = (unsigned short)(col + j);
    int ncnt = 0;
#pragma unroll
    for (int w = 0; w < 8; ++w) ncnt += s_w[w];
    __syncthreads();
    return ncnt;
}

// ---------------------------------------------------------------------------
// LIF1: reads z1(t-1) list from l1r, updates v1/i1 (with c0), writes z1(t)
// list into l1w. Per-column ascending-k chain == dense FMA chain (bitwise).
// ---------------------------------------------------------------------------
__device__ __forceinline__ void lif1_body(LifSmem* ls, int m, int tid,
    const unsigned short* __restrict__ l1r, const int* __restrict__ c1r,
    unsigned short* __restrict__ l1w, int* __restrict__ c1w,
    const float* __restrict__ W1T, const float* __restrict__ c0v,
    float* __restrict__ V, float* __restrict__ I)
{
    const int lane = tid & 31, wid = tid >> 5;
    const int col = tid * 4;
    const size_t ridx = (size_t)m * HH + col;

    int cnt = c1r[m];
    for (int i = tid; i < cnt; i += 256) ls->la[i] = l1r[(size_t)m * HH + i];
    __syncthreads();

    float acc[4] = {0.f, 0.f, 0.f, 0.f};
    sparse_accum4(acc, W1T, ls->la, cnt, col);

    float4 v4 = *(const float4*)(V + ridx);
    float4 i4 = *(const float4*)(I + ridx);
    float4 q4 = *(const float4*)(c0v + ridx);
    float vo[4] = {v4.x, v4.y, v4.z, v4.w};
    float io[4] = {i4.x, i4.y, i4.z, i4.w};
    float cq[4] = {q4.x, q4.y, q4.z, q4.w};
    float vn[4], in_[4];
    unsigned mask = 0;
#pragma unroll
    for (int j = 0; j < 4; ++j) {
        float vdec = vo[j] + 0.1f * (io[j] - vo[j]);
        float z = (vdec > 1.0f) ? 1.0f : 0.0f;
        vn[j] = (1.0f - z) * vdec;
        float idec = io[j] * 0.8f;
        in_[j] = (idec + cq[j]) + acc[j];
        if (z != 0.0f) mask |= (1u << j);
    }
    *(float4*)(V + ridx) = make_float4(vn[0], vn[1], vn[2], vn[3]);
    *(float4*)(I + ridx) = make_float4(in_[0], in_[1], in_[2], in_[3]);

    __syncthreads();
    int ncnt = build_list256(mask, ls->lb, ls->sw, lane, wid, col);
    for (int i = tid; i < ncnt; i += 256) l1w[(size_t)m * HH + i] = ls->lb[i];
    if (tid == 0) c1w[m] = ncnt;
}

// ---------------------------------------------------------------------------
// LIF2 (folded): acc = sum_{j in z1(t)} WcT[j] + bc + sum_{k in z2(t-1)} w2T[k]
// then LIF update; writes z2 dense + rebuilt list; counts spikes.
// ---------------------------------------------------------------------------
__device__ __forceinline__ void lif2_body(LifSmem* ls, int m, int tid,
    const unsigned short* __restrict__ l1r, const int* __restrict__ c1r,
    unsigned short* __restrict__ l2, int* __restrict__ c2,
    const float* __restrict__ WcT, const float* __restrict__ W2T,
    const float* __restrict__ bc,
    float* __restrict__ V, float* __restrict__ I,
    float* __restrict__ Z2, unsigned* __restrict__ cnt_out)
{
    const int lane = tid & 31, wid = tid >> 5;
    const int col = tid * 4;
    const size_t ridx = (size_t)m * HH + col;

    int cnt1 = c1r[m];
    int cnt2 = c2[m];
    for (int i = tid; i < cnt1; i += 256) ls->la[i] = l1r[(size_t)m * HH + i];
    for (int i = tid; i < cnt2; i += 256) ls->lb[i] = l2[(size_t)m * HH + i];
    __syncthreads();

    float acc[4] = {0.f, 0.f, 0.f, 0.f};
    sparse_accum4(acc, WcT, ls->la, cnt1, col);        // z1 @ Wc^T
    float4 b4 = *(const float4*)(bc + col);
    acc[0] += b4.x; acc[1] += b4.y; acc[2] += b4.z; acc[3] += b4.w;
    sparse_accum4(acc, W2T, ls->lb, cnt2, col);        // z2_old @ w2rec^T

    float4 v4 = *(const float4*)(V + ridx);
    float4 i4 = *(const float4*)(I + ridx);
    float vo[4] = {v4.x, v4.y, v4.z, v4.w};
    float io[4] = {i4.x, i4.y, i4.z, i4.w};
    float vn[4], in_[4], zn[4];
    unsigned mask = 0;
#pragma unroll
    for (int j = 0; j < 4; ++j) {
        float vdec = vo[j] + 0.1f * (io[j] - vo[j]);
        float z = (vdec > 1.0f) ? 1.0f : 0.0f;
        vn[j] = (1.0f - z) * vdec;
        float idec = io[j] * 0.8f;
        in_[j] = idec + acc[j];
        zn[j] = z;
        if (z != 0.0f) mask |= (1u << j);
    }
    *(float4*)(V + ridx)  = make_float4(vn[0], vn[1], vn[2], vn[3]);
    *(float4*)(I + ridx)  = make_float4(in_[0], in_[1], in_[2], in_[3]);
    *(float4*)(Z2 + ridx) = make_float4(zn[0], zn[1], zn[2], zn[3]);

    __syncthreads();
    int ncnt = build_list256(mask, ls->lb, ls->sw, lane, wid, col);
    for (int i = tid; i < ncnt; i += 256) l2[(size_t)m * HH + i] = ls->lb[i];
    if (tid == 0) {
        c2[m] = ncnt;
        atomicAdd(cnt_out, (unsigned)ncnt);
    }
}

// ---------------------------------------------------------------------------
__global__ __launch_bounds__(256)
void lif1_k(const unsigned short* l1r, const int* c1r,
            unsigned short* l1w, int* c1w,
            const float* W1T, const float* c0v, float* V, float* I)
{
    __shared__ LifSmem ls;
    lif1_body(&ls, blockIdx.x, threadIdx.x, l1r, c1r, l1w, c1w, W1T, c0v, V, I);
}

// Fused: blocks [0,4096) = lif2(t); [4096,8192) = lif1(t+1) (if enabled)
__global__ __launch_bounds__(256)
void fused_step(const unsigned short* __restrict__ l1r, const int* __restrict__ c1r,
                unsigned short* __restrict__ l1w, int* __restrict__ c1w,
                unsigned short* __restrict__ l2, int* __restrict__ c2,
                const float* __restrict__ W1T, const float* __restrict__ WcT,
                const float* __restrict__ W2T, const float* __restrict__ bc,
                const float* __restrict__ c0v,
                float* __restrict__ v1, float* __restrict__ i1,
                float* __restrict__ v2, float* __restrict__ i2,
                float* __restrict__ z2, unsigned* __restrict__ cnt_out,
                int do_lif1)
{
    __shared__ LifSmem ls;
    const int bid = blockIdx.x, tid = threadIdx.x;
    if (bid < LIF_BLKS) {
        lif2_body(&ls, bid, tid, l1r, c1r, l2, c2, WcT, W2T, bc, v2, i2, z2, cnt_out);
    } else if (do_lif1) {
        lif1_body(&ls, bid - LIF_BLKS, tid, l1r, c1r, l1w, c1w, W1T, c0v, v1, i1);
    }
}

// ---------------------------------------------------------------------------
__global__ void finalize(const float* __restrict__ zlast,
                         const unsigned* __restrict__ cnt,
                         float* __restrict__ out, int n, int out_size)
{
    size_t i = (size_t)blockIdx.x * blockDim.x + threadIdx.x;
    size_t st = (size_t)gridDim.x * blockDim.x;
    for (size_t k = i; k < (size_t)n; k += st) out[k] = zlast[k];
    if (i == 0 && out_size > n) {
        float rs = 0.f;
        for (int t = 0; t < TW; ++t)
            rs += (float)cnt[t] * (1.0f / 4194304.0f);   // exact: /2^22
        out[n] = rs * (1.0f / 16.0f);                     // inv_T, exact
    }
}

// ---------------------------------------------------------------------------
extern "C" void kernel_launch(void* const* d_in, const int* in_sizes, int n_in,
                              void* d_out, int out_size)
{
    const float* x     = (const float*)d_in[0];
    const float* fc1w  = (const float*)d_in[1];
    const float* fc1b  = (const float*)d_in[2];
    const float* w1in  = (const float*)d_in[3];
    const float* w1rec = (const float*)d_in[4];
    const float* fc2w  = (const float*)d_in[5];
    const float* fc2b  = (const float*)d_in[6];
    const float* w2in  = (const float*)d_in[7];
    const float* w2rec = (const float*)d_in[8];
    (void)in_sizes; (void)n_in;

    float *z0, *c0, *v1, *i1, *v2, *i2, *z2, *w1T, *f2T, *w2T, *Wc, *WcT, *bc;
    unsigned short *l1[2], *l2;
    int *c1[2], *c2;
    unsigned* cnt;
    cudaGetSymbolAddress((void**)&z0, g_z0);
    cudaGetSymbolAddress((void**)&c0, g_c0);
    cudaGetSymbolAddress((void**)&v1, g_v1);
    cudaGetSymbolAddress((void**)&i1, g_i1);
    cudaGetSymbolAddress((void**)&v2, g_v2);
    cudaGetSymbolAddress((void**)&i2, g_i2);
    cudaGetSymbolAddress((void**)&z2, g_z2);
    cudaGetSymbolAddress((void**)&w1T, g_w1T);
    cudaGetSymbolAddress((void**)&f2T, g_f2T);
    cudaGetSymbolAddress((void**)&w2T, g_w2T);
    cudaGetSymbolAddress((void**)&Wc, g_Wc);
    cudaGetSymbolAddress((void**)&WcT, g_WcT);
    cudaGetSymbolAddress((void**)&bc, g_bc);
    {
        unsigned short* p;
        cudaGetSymbolAddress((void**)&p, g_l1);
        l1[0] = p; l1[1] = p + NEL;
        cudaGetSymbolAddress((void**)&l2, g_l2);
        int* q;
        cudaGetSymbolAddress((void**)&q, g_c1);
        c1[0] = q; c1[1] = q + BSZ;
        cudaGetSymbolAddress((void**)&c2, g_c2);
    }
    cudaGetSymbolAddress((void**)&cnt, g_cnt);

    dim3 gbig(HH / BN, BSZ / BM);   // (8, 32)
    dim3 ghh(HH / BN, HH / BM);     // (8, 8)
    dim3 tgrid(32, 32), tblk(32, 8);

    init_state<<<256, 256>>>();

    // ---- one-time prologue ----
    sgemm0<<<gbig, 256>>>(x, fc1w, fc1b, z0, DD, HH);     // z0 = fc1(x)
    sgemm0<<<gbig, 256>>>(z0, w1in, nullptr, c0, HH, HH); // c0 = z0@w1in^T
    transpose_hh<<<tgrid, tblk>>>(w1rec, w1T);
    transpose_hh<<<tgrid, tblk>>>(fc2w,  f2T);
    transpose_hh<<<tgrid, tblk>>>(w2rec, w2T);
    sgemm0<<<ghh, 256>>>(w2in, f2T, nullptr, Wc, HH, HH); // Wc = w2in@fc2w
    transpose_hh<<<tgrid, tblk>>>(Wc, WcT);
    bias_prop<<<HH, 256>>>(w2in, fc2b, bc);               // bc = w2in@fc2b

    // ---- pipeline head: lif1(0): reads l1[1] (empty), writes l1[0] ----
    lif1_k<<<LIF_BLKS, 256>>>(l1[1], c1[1], l1[0], c1[0], w1T, c0, v1, i1);

    // ---- fused loop: {lif2(t), lif1(t+1)} — z1(t) list lives in l1[t&1] ----
    for (int t = 0; t < TW; ++t) {
        fused_step<<<2 * LIF_BLKS, 256>>>(
            l1[t & 1], c1[t & 1],             // z1(t) list (read by both roles)
            l1[(t + 1) & 1], c1[(t + 1) & 1], // z1(t+1) list (written by lif1)
            l2, c2,
            w1T, WcT, w2T, bc, c0,
            v1, i1, v2, i2, z2, cnt + t,
            (t < TW - 1) ? 1 : 0);
    }

    finalize<<<512, 256>>>(z2, cnt, (float*)d_out, NEL, out_size);
}